// round 1
// baseline (speedup 1.0000x reference)
#include <cuda_runtime.h>
#include <math.h>

// Problem constants
#define B_ 8
#define T_ 8192
#define C_ 256
#define H_ 8
#define G_ 64
#define D_ 32
#define N_ (B_*T_)       // 65536 rows
#define NCH 64           // pooling chunks per (b,h)
#define CHUNK 128        // rows per pooling chunk (NCH*CHUNK == T_)

// ---------------- scratch (static device globals; no runtime allocs) ----------
__device__ float g_tmp[(size_t)N_ * C_];            // in_proj output (n, c)  64MB
__device__ float g_sw[(size_t)N_ * H_ * G_];        // slice weights (n, h, g) 128MB
__device__ float g_part[(size_t)B_ * H_ * NCH * G_ * D_];  // pooling partials 32MB
__device__ float g_pnorm[(size_t)B_ * H_ * NCH * G_];      // norm partials
__device__ float g_M[(size_t)B_ * (H_ * G_) * C_];  // folded (os @ W_out) per batch: (512,256)

// ---------------- packed fp32 FMA (2 MACs / instr on sm_103a) ------------------
__device__ __forceinline__ float2 ffma2(float2 a, float2 b, float2 c) {
    float2 d;
    asm("fma.rn.f32x2 %0, %1, %2, %3;"
        : "=l"(reinterpret_cast<unsigned long long&>(d))
        : "l"(reinterpret_cast<unsigned long long&>(a)),
          "l"(reinterpret_cast<unsigned long long&>(b)),
          "l"(reinterpret_cast<unsigned long long&>(c)));
    return d;
}

// ---------------- generic 128x128 SGEMM with bias (row-major) ------------------
// C[M,N] = A[M,K] @ B[K,N] + bias;  M%128==0, N%128==0, K%16==0
__global__ __launch_bounds__(256) void sgemm_bias_kernel(
    const float* __restrict__ A, int lda,
    const float* __restrict__ Bm, int ldb,
    float* __restrict__ Cm, int ldc,
    const float* __restrict__ bias, int K)
{
    __shared__ float As[16][128];   // transposed A tile: As[k][m]
    __shared__ float Bs[16][128];   // Bs[k][n]

    const int tid = threadIdx.x;
    const int tx = tid & 15;        // n-group
    const int ty = tid >> 4;        // m-group

    const float* Ab = A + (size_t)blockIdx.y * 128 * lda;
    const float* Bb = Bm + (size_t)blockIdx.x * 128;

    float2 acc[4][8];
    #pragma unroll
    for (int mp = 0; mp < 4; mp++)
        #pragma unroll
        for (int n = 0; n < 8; n++) acc[mp][n] = make_float2(0.f, 0.f);

    for (int kt = 0; kt < K; kt += 16) {
        #pragma unroll
        for (int p = 0; p < 2; p++) {
            int r = (tid >> 2) + p * 64;
            float4 va = *(const float4*)(Ab + (size_t)r * lda + kt + (tid & 3) * 4);
            int c = (tid & 3) * 4;
            As[c][r] = va.x; As[c + 1][r] = va.y; As[c + 2][r] = va.z; As[c + 3][r] = va.w;
        }
        #pragma unroll
        for (int p = 0; p < 2; p++) {
            int r = (tid >> 5) + p * 8;
            *(float4*)&Bs[r][(tid & 31) * 4] =
                *(const float4*)(Bb + (size_t)(kt + r) * ldb + (tid & 31) * 4);
        }
        __syncthreads();
        #pragma unroll
        for (int kk = 0; kk < 16; kk++) {
            float2 a2[4];
            const float2* Ar = (const float2*)&As[kk][ty * 8];
            #pragma unroll
            for (int mp = 0; mp < 4; mp++) a2[mp] = Ar[mp];
            float4 b0 = *(const float4*)&Bs[kk][tx * 8];
            float4 b1 = *(const float4*)&Bs[kk][tx * 8 + 4];
            float bb[8] = {b0.x, b0.y, b0.z, b0.w, b1.x, b1.y, b1.z, b1.w};
            #pragma unroll
            for (int n = 0; n < 8; n++) {
                float2 bv = make_float2(bb[n], bb[n]);
                #pragma unroll
                for (int mp = 0; mp < 4; mp++) acc[mp][n] = ffma2(a2[mp], bv, acc[mp][n]);
            }
        }
        __syncthreads();
    }

    int row0 = blockIdx.y * 128 + ty * 8;
    int col0 = blockIdx.x * 128 + tx * 8;
    float bsv[8];
    #pragma unroll
    for (int n = 0; n < 8; n++) bsv[n] = bias ? bias[col0 + n] : 0.f;
    #pragma unroll
    for (int mp = 0; mp < 4; mp++) {
        #pragma unroll
        for (int n = 0; n < 8; n++) {
            Cm[(size_t)(row0 + 2 * mp) * ldc + col0 + n]     = acc[mp][n].x + bsv[n];
            Cm[(size_t)(row0 + 2 * mp + 1) * ldc + col0 + n] = acc[mp][n].y + bsv[n];
        }
    }
}

// ---------------- K2: slice weights (softmax over G per (n,h)) -----------------
__global__ __launch_bounds__(256) void slicew_kernel(
    const float* __restrict__ Wslice,   // (D,G) row-major
    const float* __restrict__ bslice,   // (G)
    const float* __restrict__ temp)     // (H)
{
    __shared__ float Ws[D_ * G_];
    __shared__ float bs[G_];
    __shared__ float it[H_];
    int tid = threadIdx.x;
    #pragma unroll
    for (int i = 0; i < 8; i++) Ws[tid + i * 256] = Wslice[tid + i * 256];
    if (tid < G_) bs[tid] = bslice[tid];
    if (tid < H_) it[tid] = 1.f / temp[tid];
    __syncthreads();

    int gid = blockIdx.x * 256 + tid;   // (n,h) pair
    int n = gid >> 3, h = gid & 7;

    float x[D_];
    const float4* xr = (const float4*)(g_tmp + (size_t)n * C_ + h * D_);
    #pragma unroll
    for (int i = 0; i < 8; i++) {
        float4 v = xr[i];
        x[4 * i] = v.x; x[4 * i + 1] = v.y; x[4 * i + 2] = v.z; x[4 * i + 3] = v.w;
    }

    float2 lg[G_ / 2];
    const float2* bs2 = (const float2*)bs;
    #pragma unroll
    for (int j = 0; j < G_ / 2; j++) lg[j] = bs2[j];

    const float2* Ws2 = (const float2*)Ws;
    for (int d = 0; d < D_; d++) {
        float2 xv = make_float2(x[d], x[d]);
        #pragma unroll
        for (int j = 0; j < G_ / 2; j++) lg[j] = ffma2(xv, Ws2[d * (G_ / 2) + j], lg[j]);
    }

    float sc = it[h];
    float mx = -1e30f;
    #pragma unroll
    for (int j = 0; j < G_ / 2; j++) {
        lg[j].x *= sc; lg[j].y *= sc;
        mx = fmaxf(mx, fmaxf(lg[j].x, lg[j].y));
    }
    float sum = 0.f;
    #pragma unroll
    for (int j = 0; j < G_ / 2; j++) {
        lg[j].x = __expf(lg[j].x - mx);
        lg[j].y = __expf(lg[j].y - mx);
        sum += lg[j].x + lg[j].y;
    }
    float inv = 1.f / sum;

    float4* dst = (float4*)(g_sw + (size_t)n * (H_ * G_) + h * G_);
    #pragma unroll
    for (int j = 0; j < 16; j++)
        dst[j] = make_float4(lg[2 * j].x * inv, lg[2 * j].y * inv,
                             lg[2 * j + 1].x * inv, lg[2 * j + 1].y * inv);
}

// ---------------- K3: chunked pooling partials (deterministic) -----------------
__global__ __launch_bounds__(256) void pool_kernel()
{
    __shared__ float xs[CHUNK][D_];
    __shared__ float sws[CHUNK][G_];
    int chunk = blockIdx.x, bh = blockIdx.y;
    int b = bh >> 3, h = bh & 7;
    int tid = threadIdx.x;
    size_t nbase = (size_t)b * T_ + (size_t)chunk * CHUNK;

    #pragma unroll
    for (int p = 0; p < 4; p++) {
        int r = (tid >> 3) + p * 32;
        ((float4*)xs[r])[tid & 7] =
            ((const float4*)(g_tmp + (nbase + r) * C_ + h * D_))[tid & 7];
    }
    #pragma unroll
    for (int p = 0; p < 8; p++) {
        int r = (tid >> 4) + p * 16;
        ((float4*)sws[r])[tid & 15] =
            ((const float4*)(g_sw + (nbase + r) * (H_ * G_) + h * G_))[tid & 15];
    }
    __syncthreads();

    int d = tid & 31, gb = (tid >> 5) * 8;
    float2 acc[4] = {{0.f,0.f},{0.f,0.f},{0.f,0.f},{0.f,0.f}};
    for (int r = 0; r < CHUNK; r++) {
        float2 xv = make_float2(xs[r][d], xs[r][d]);
        const float2* swr = (const float2*)&sws[r][gb];
        #pragma unroll
        for (int j = 0; j < 4; j++) acc[j] = ffma2(xv, swr[j], acc[j]);
    }
    size_t pbase = ((size_t)bh * NCH + chunk) * (G_ * D_);
    #pragma unroll
    for (int j = 0; j < 4; j++) {
        g_part[pbase + (size_t)(gb + 2 * j) * D_ + d]     = acc[j].x;
        g_part[pbase + (size_t)(gb + 2 * j + 1) * D_ + d] = acc[j].y;
    }
    if (tid < G_) {
        float s = 0.f;
        for (int r = 0; r < CHUNK; r++) s += sws[r][tid];
        g_pnorm[((size_t)bh * NCH + chunk) * G_ + tid] = s;
    }
}

// ------- K4: reduce partials -> tokens -> qkv -> GxG attention -> fold W_out ---
__global__ __launch_bounds__(256) void attn_tiny_kernel(
    const float* __restrict__ Wq, const float* __restrict__ bq,
    const float* __restrict__ Wk, const float* __restrict__ bk,
    const float* __restrict__ Wv, const float* __restrict__ bv,
    const float* __restrict__ Wout)
{
    __shared__ float tok[G_][D_ + 1];   // later reused for out_slice
    __shared__ float qs[G_][D_ + 1];
    __shared__ float ks[G_][D_ + 1];
    __shared__ float vs[G_][D_ + 1];
    __shared__ float norms[G_];

    int bh = blockIdx.x;
    int b = bh >> 3, h = bh & 7;
    int tid = threadIdx.x;

    if (tid < G_) {
        float s = 0.f;
        for (int ch = 0; ch < NCH; ch++)
            s += g_pnorm[((size_t)bh * NCH + ch) * G_ + tid];
        norms[tid] = s + 1e-5f;
    }
    __syncthreads();

    #pragma unroll
    for (int i = 0; i < 8; i++) {
        int c = tid + i * 256;
        int g = c >> 5, d = c & 31;
        float s = 0.f;
        for (int ch = 0; ch < NCH; ch++)
            s += g_part[((size_t)bh * NCH + ch) * (G_ * D_) + c];
        tok[g][d] = s / norms[g];
    }
    __syncthreads();

    // q,k,v = token @ W + b   (each (G,D) @ (D,D))
    #pragma unroll
    for (int i = 0; i < 8; i++) {
        int c = tid + i * 256;
        int g = c >> 5, d = c & 31;
        float aq = bq[d], ak = bk[d], av = bv[d];
        for (int e = 0; e < D_; e++) {
            float t = tok[g][e];
            aq += t * Wq[e * D_ + d];
            ak += t * Wk[e * D_ + d];
            av += t * Wv[e * D_ + d];
        }
        qs[g][d] = aq; ks[g][d] = ak; vs[g][d] = av;
    }
    __syncthreads();

    // attention rows: thread g owns row g (G=64 threads)
    if (tid < G_) {
        float qr[D_];
        #pragma unroll
        for (int d = 0; d < D_; d++) qr[d] = qs[tid][d];
        float s[G_];
        float mx = -1e30f;
        #pragma unroll
        for (int j = 0; j < G_; j++) {
            float a = 0.f;
            #pragma unroll
            for (int d = 0; d < D_; d++) a += qr[d] * ks[j][d];
            a *= 0.17677669529663687f;   // 1/sqrt(32)
            s[j] = a; mx = fmaxf(mx, a);
        }
        float sum = 0.f;
        #pragma unroll
        for (int j = 0; j < G_; j++) { s[j] = __expf(s[j] - mx); sum += s[j]; }
        float inv = 1.f / sum;
        #pragma unroll
        for (int d = 0; d < D_; d++) {
            float a = 0.f;
            #pragma unroll
            for (int j = 0; j < G_; j++) a += s[j] * vs[j][d];
            tok[tid][d] = a * inv;       // out_slice row
        }
    }
    __syncthreads();

    // fold: M[h*G+g, col] = sum_d os[g][d] * W_out[h*D+d, col]
    #pragma unroll
    for (int i = 0; i < 64; i++) {
        int c = tid + i * 256;
        int g = c >> 8, col = c & 255;
        float a = 0.f;
        #pragma unroll
        for (int d = 0; d < D_; d++) a += tok[g][d] * Wout[(h * D_ + d) * C_ + col];
        g_M[((size_t)b * (H_ * G_) + h * G_ + g) * C_ + col] = a;
    }
}

// ---------------- launch --------------------------------------------------------
extern "C" void kernel_launch(void* const* d_in, const int* in_sizes, int n_in,
                              void* d_out, int out_size)
{
    const float* x_q    = (const float*)d_in[0];
    const float* W_in   = (const float*)d_in[3];
    const float* b_in   = (const float*)d_in[4];
    const float* W_sl   = (const float*)d_in[5];
    const float* b_sl   = (const float*)d_in[6];
    const float* temp   = (const float*)d_in[7];
    const float* W_q    = (const float*)d_in[8];
    const float* b_q    = (const float*)d_in[9];
    const float* W_k    = (const float*)d_in[10];
    const float* b_k    = (const float*)d_in[11];
    const float* W_v    = (const float*)d_in[12];
    const float* b_v    = (const float*)d_in[13];
    const float* W_out  = (const float*)d_in[14];
    const float* b_out  = (const float*)d_in[15];
    float* out = (float*)d_out;

    float *tmp_p, *sw_p, *M_p;
    cudaGetSymbolAddress((void**)&tmp_p, g_tmp);
    cudaGetSymbolAddress((void**)&sw_p, g_sw);
    cudaGetSymbolAddress((void**)&M_p, g_M);

    // K1: tmp = x_q @ W_in + b_in   (65536x256 @ 256x256)
    sgemm_bias_kernel<<<dim3(C_ / 128, N_ / 128), 256>>>(
        x_q, C_, W_in, C_, tmp_p, C_, b_in, C_);

    // K2: slice weights (softmax over G)
    slicew_kernel<<<(N_ * H_) / 256, 256>>>(W_sl, b_sl, temp);

    // K3: pooling partials
    pool_kernel<<<dim3(NCH, B_ * H_), 256>>>();

    // K4: tiny attention + fold W_out into M
    attn_tiny_kernel<<<B_ * H_, 256>>>(W_q, b_q, W_k, b_k, W_v, b_v, W_out);

    // K5: out[b] = SW[b](8192x512) @ M[b](512x256) + b_out
    for (int b = 0; b < B_; b++) {
        sgemm_bias_kernel<<<dim3(C_ / 128, T_ / 128), 256>>>(
            sw_p + (size_t)b * T_ * (H_ * G_), H_ * G_,
            M_p + (size_t)b * (H_ * G_) * C_, C_,
            out + (size_t)b * T_ * C_, C_,
            b_out, H_ * G_);
    }
}

// round 2
// speedup vs baseline: 1.1828x; 1.1828x over previous
#include <cuda_runtime.h>
#include <math.h>

// Problem constants
#define B_ 8
#define T_ 8192
#define C_ 256
#define H_ 8
#define G_ 64
#define D_ 32
#define N_ (B_*T_)       // 65536 rows
#define CHUNK 128        // rows per pooling sub-chunk
#define SUBC 4           // sub-chunks accumulated per pool block
#define NCH2 16          // partial sets per (b,h)  (NCH2*SUBC*CHUNK == T_)

// ---------------- scratch (static device globals; no runtime allocs) ----------
__device__ float g_tmp[(size_t)N_ * C_];            // in_proj output (n, c)  64MB
__device__ float g_sw[(size_t)N_ * H_ * G_];        // slice weights (n, h, g) 128MB
__device__ float g_part[(size_t)B_ * H_ * NCH2 * G_ * D_];  // pooling partials 8MB
__device__ float g_pnorm[(size_t)B_ * H_ * NCH2 * G_];      // norm partials
__device__ float g_M[(size_t)B_ * (H_ * G_) * C_];  // folded (os @ W_out) per batch: (512,256)

// ---------------- packed fp32 FMA (2 MACs / instr on sm_103a) ------------------
__device__ __forceinline__ float2 ffma2(float2 a, float2 b, float2 c) {
    float2 d;
    asm("fma.rn.f32x2 %0, %1, %2, %3;"
        : "=l"(reinterpret_cast<unsigned long long&>(d))
        : "l"(reinterpret_cast<unsigned long long&>(a)),
          "l"(reinterpret_cast<unsigned long long&>(b)),
          "l"(reinterpret_cast<unsigned long long&>(c)));
    return d;
}

// ---------------- generic batched 128x128 SGEMM with bias (row-major) ----------
// C[z][M,N] = A[z][M,K] @ B[z][K,N] + bias;  M%128==0, N%128==0, K%16==0
__global__ __launch_bounds__(256) void sgemm_bias_kernel(
    const float* __restrict__ A, int lda, size_t strideA,
    const float* __restrict__ Bm, int ldb, size_t strideB,
    float* __restrict__ Cm, int ldc, size_t strideC,
    const float* __restrict__ bias, int K)
{
    __shared__ float As[16][128];   // transposed A tile: As[k][m]
    __shared__ float Bs[16][128];   // Bs[k][n]

    const int tid = threadIdx.x;
    const int tx = tid & 15;        // n-group
    const int ty = tid >> 4;        // m-group

    const float* Ab = A + (size_t)blockIdx.z * strideA + (size_t)blockIdx.y * 128 * lda;
    const float* Bb = Bm + (size_t)blockIdx.z * strideB + (size_t)blockIdx.x * 128;
    float* Cb = Cm + (size_t)blockIdx.z * strideC;

    float2 acc[4][8];
    #pragma unroll
    for (int mp = 0; mp < 4; mp++)
        #pragma unroll
        for (int n = 0; n < 8; n++) acc[mp][n] = make_float2(0.f, 0.f);

    for (int kt = 0; kt < K; kt += 16) {
        #pragma unroll
        for (int p = 0; p < 2; p++) {
            int r = (tid >> 2) + p * 64;
            float4 va = *(const float4*)(Ab + (size_t)r * lda + kt + (tid & 3) * 4);
            int c = (tid & 3) * 4;
            As[c][r] = va.x; As[c + 1][r] = va.y; As[c + 2][r] = va.z; As[c + 3][r] = va.w;
        }
        #pragma unroll
        for (int p = 0; p < 2; p++) {
            int r = (tid >> 5) + p * 8;
            *(float4*)&Bs[r][(tid & 31) * 4] =
                *(const float4*)(Bb + (size_t)(kt + r) * ldb + (tid & 31) * 4);
        }
        __syncthreads();
        #pragma unroll
        for (int kk = 0; kk < 16; kk++) {
            float2 a2[4];
            const float2* Ar = (const float2*)&As[kk][ty * 8];
            #pragma unroll
            for (int mp = 0; mp < 4; mp++) a2[mp] = Ar[mp];
            float4 b0 = *(const float4*)&Bs[kk][tx * 8];
            float4 b1 = *(const float4*)&Bs[kk][tx * 8 + 4];
            float bb[8] = {b0.x, b0.y, b0.z, b0.w, b1.x, b1.y, b1.z, b1.w};
            #pragma unroll
            for (int n = 0; n < 8; n++) {
                float2 bv = make_float2(bb[n], bb[n]);
                #pragma unroll
                for (int mp = 0; mp < 4; mp++) acc[mp][n] = ffma2(a2[mp], bv, acc[mp][n]);
            }
        }
        __syncthreads();
    }

    int row0 = blockIdx.y * 128 + ty * 8;
    int col0 = blockIdx.x * 128 + tx * 8;
    float bsv[8];
    #pragma unroll
    for (int n = 0; n < 8; n++) bsv[n] = bias ? bias[col0 + n] : 0.f;
    #pragma unroll
    for (int mp = 0; mp < 4; mp++) {
        #pragma unroll
        for (int n = 0; n < 8; n++) {
            Cb[(size_t)(row0 + 2 * mp) * ldc + col0 + n]     = acc[mp][n].x + bsv[n];
            Cb[(size_t)(row0 + 2 * mp + 1) * ldc + col0 + n] = acc[mp][n].y + bsv[n];
        }
    }
}

// ---------------- K2: slice weights (softmax over G per (n,h)) -----------------
__global__ __launch_bounds__(256) void slicew_kernel(
    const float* __restrict__ Wslice,   // (D,G) row-major
    const float* __restrict__ bslice,   // (G)
    const float* __restrict__ temp)     // (H)
{
    __shared__ float Ws[D_ * G_];
    __shared__ float bs[G_];
    __shared__ float it[H_];
    int tid = threadIdx.x;
    #pragma unroll
    for (int i = 0; i < 8; i++) Ws[tid + i * 256] = Wslice[tid + i * 256];
    if (tid < G_) bs[tid] = bslice[tid];
    if (tid < H_) it[tid] = 1.f / temp[tid];
    __syncthreads();

    int gid = blockIdx.x * 256 + tid;   // (n,h) pair
    int n = gid >> 3, h = gid & 7;

    float x[D_];
    const float4* xr = (const float4*)(g_tmp + (size_t)n * C_ + h * D_);
    #pragma unroll
    for (int i = 0; i < 8; i++) {
        float4 v = xr[i];
        x[4 * i] = v.x; x[4 * i + 1] = v.y; x[4 * i + 2] = v.z; x[4 * i + 3] = v.w;
    }

    float2 lg[G_ / 2];
    const float2* bs2 = (const float2*)bs;
    #pragma unroll
    for (int j = 0; j < G_ / 2; j++) lg[j] = bs2[j];

    const float2* Ws2 = (const float2*)Ws;
    for (int d = 0; d < D_; d++) {
        float2 xv = make_float2(x[d], x[d]);
        #pragma unroll
        for (int j = 0; j < G_ / 2; j++) lg[j] = ffma2(xv, Ws2[d * (G_ / 2) + j], lg[j]);
    }

    float sc = it[h];
    float mx = -1e30f;
    #pragma unroll
    for (int j = 0; j < G_ / 2; j++) {
        lg[j].x *= sc; lg[j].y *= sc;
        mx = fmaxf(mx, fmaxf(lg[j].x, lg[j].y));
    }
    float sum = 0.f;
    #pragma unroll
    for (int j = 0; j < G_ / 2; j++) {
        lg[j].x = __expf(lg[j].x - mx);
        lg[j].y = __expf(lg[j].y - mx);
        sum += lg[j].x + lg[j].y;
    }
    float inv = 1.f / sum;

    float4* dst = (float4*)(g_sw + (size_t)n * (H_ * G_) + h * G_);
    #pragma unroll
    for (int j = 0; j < 16; j++)
        dst[j] = make_float4(lg[2 * j].x * inv, lg[2 * j].y * inv,
                             lg[2 * j + 1].x * inv, lg[2 * j + 1].y * inv);
}

// ---------------- K3: chunked pooling partials (deterministic) -----------------
// grid (NCH2, B*H): each block accumulates SUBC sub-chunks of CHUNK rows.
__global__ __launch_bounds__(256) void pool_kernel()
{
    __shared__ float xs[CHUNK][D_];
    __shared__ float sws[CHUNK][G_];
    int pc = blockIdx.x, bh = blockIdx.y;
    int b = bh >> 3, h = bh & 7;
    int tid = threadIdx.x;

    int d = tid & 31, gb = (tid >> 5) * 8;
    float2 acc[4] = {{0.f,0.f},{0.f,0.f},{0.f,0.f},{0.f,0.f}};
    float nsum = 0.f;

    for (int sc = 0; sc < SUBC; sc++) {
        size_t nbase = (size_t)b * T_ + ((size_t)pc * SUBC + sc) * CHUNK;
        #pragma unroll
        for (int p = 0; p < 4; p++) {
            int r = (tid >> 3) + p * 32;
            ((float4*)xs[r])[tid & 7] =
                ((const float4*)(g_tmp + (nbase + r) * C_ + h * D_))[tid & 7];
        }
        #pragma unroll
        for (int p = 0; p < 8; p++) {
            int r = (tid >> 4) + p * 16;
            ((float4*)sws[r])[tid & 15] =
                ((const float4*)(g_sw + (nbase + r) * (H_ * G_) + h * G_))[tid & 15];
        }
        __syncthreads();

        for (int r = 0; r < CHUNK; r++) {
            float2 xv = make_float2(xs[r][d], xs[r][d]);
            const float2* swr = (const float2*)&sws[r][gb];
            #pragma unroll
            for (int j = 0; j < 4; j++) acc[j] = ffma2(xv, swr[j], acc[j]);
        }
        if (tid < G_) {
            float s = 0.f;
            for (int r = 0; r < CHUNK; r++) s += sws[r][tid];
            nsum += s;
        }
        __syncthreads();
    }

    size_t pbase = ((size_t)bh * NCH2 + pc) * (G_ * D_);
    #pragma unroll
    for (int j = 0; j < 4; j++) {
        g_part[pbase + (size_t)(gb + 2 * j) * D_ + d]     = acc[j].x;
        g_part[pbase + (size_t)(gb + 2 * j + 1) * D_ + d] = acc[j].y;
    }
    if (tid < G_)
        g_pnorm[((size_t)bh * NCH2 + pc) * G_ + tid] = nsum;
}

// ------- K4: reduce partials -> tokens -> qkv -> GxG attention -> fold W_out ---
__global__ __launch_bounds__(256) void attn_tiny_kernel(
    const float* __restrict__ Wq, const float* __restrict__ bq,
    const float* __restrict__ Wk, const float* __restrict__ bk,
    const float* __restrict__ Wv, const float* __restrict__ bv,
    const float* __restrict__ Wout)
{
    __shared__ float tok[G_][D_ + 1];   // later reused for out_slice
    __shared__ float qs[G_][D_ + 1];
    __shared__ float ks[G_][D_ + 1];
    __shared__ float vs[G_][D_ + 1];
    __shared__ float norms[G_];

    int bh = blockIdx.x;
    int b = bh >> 3, h = bh & 7;
    int tid = threadIdx.x;

    if (tid < G_) {
        float s = 0.f;
        for (int ch = 0; ch < NCH2; ch++)
            s += g_pnorm[((size_t)bh * NCH2 + ch) * G_ + tid];
        norms[tid] = s + 1e-5f;
    }
    __syncthreads();

    #pragma unroll
    for (int i = 0; i < 8; i++) {
        int c = tid + i * 256;
        int g = c >> 5, d = c & 31;
        float s = 0.f;
        for (int ch = 0; ch < NCH2; ch++)
            s += g_part[((size_t)bh * NCH2 + ch) * (G_ * D_) + c];
        tok[g][d] = s / norms[g];
    }
    __syncthreads();

    // q,k,v = token @ W + b   (each (G,D) @ (D,D))
    #pragma unroll
    for (int i = 0; i < 8; i++) {
        int c = tid + i * 256;
        int g = c >> 5, d = c & 31;
        float aq = bq[d], ak = bk[d], av = bv[d];
        for (int e = 0; e < D_; e++) {
            float t = tok[g][e];
            aq += t * Wq[e * D_ + d];
            ak += t * Wk[e * D_ + d];
            av += t * Wv[e * D_ + d];
        }
        qs[g][d] = aq; ks[g][d] = ak; vs[g][d] = av;
    }
    __syncthreads();

    // attention rows: thread g owns row g (G=64 threads)
    if (tid < G_) {
        float qr[D_];
        #pragma unroll
        for (int d = 0; d < D_; d++) qr[d] = qs[tid][d];
        float s[G_];
        float mx = -1e30f;
        #pragma unroll
        for (int j = 0; j < G_; j++) {
            float a = 0.f;
            #pragma unroll
            for (int d = 0; d < D_; d++) a += qr[d] * ks[j][d];
            a *= 0.17677669529663687f;   // 1/sqrt(32)
            s[j] = a; mx = fmaxf(mx, a);
        }
        float sum = 0.f;
        #pragma unroll
        for (int j = 0; j < G_; j++) { s[j] = __expf(s[j] - mx); sum += s[j]; }
        float inv = 1.f / sum;
        #pragma unroll
        for (int d = 0; d < D_; d++) {
            float a = 0.f;
            #pragma unroll
            for (int j = 0; j < G_; j++) a += s[j] * vs[j][d];
            tok[tid][d] = a * inv;       // out_slice row
        }
    }
    __syncthreads();

    // fold: M[h*G+g, col] = sum_d os[g][d] * W_out[h*D+d, col]
    #pragma unroll
    for (int i = 0; i < 64; i++) {
        int c = tid + i * 256;
        int g = c >> 8, col = c & 255;
        float a = 0.f;
        #pragma unroll
        for (int d = 0; d < D_; d++) a += tok[g][d] * Wout[(h * D_ + d) * C_ + col];
        g_M[((size_t)b * (H_ * G_) + h * G_ + g) * C_ + col] = a;
    }
}

// ---------------- launch --------------------------------------------------------
extern "C" void kernel_launch(void* const* d_in, const int* in_sizes, int n_in,
                              void* d_out, int out_size)
{
    const float* x_q    = (const float*)d_in[0];
    const float* W_in   = (const float*)d_in[3];
    const float* b_in   = (const float*)d_in[4];
    const float* W_sl   = (const float*)d_in[5];
    const float* b_sl   = (const float*)d_in[6];
    const float* temp   = (const float*)d_in[7];
    const float* W_q    = (const float*)d_in[8];
    const float* b_q    = (const float*)d_in[9];
    const float* W_k    = (const float*)d_in[10];
    const float* b_k    = (const float*)d_in[11];
    const float* W_v    = (const float*)d_in[12];
    const float* b_v    = (const float*)d_in[13];
    const float* W_out  = (const float*)d_in[14];
    const float* b_out  = (const float*)d_in[15];
    float* out = (float*)d_out;

    float *tmp_p, *sw_p, *M_p;
    cudaGetSymbolAddress((void**)&tmp_p, g_tmp);
    cudaGetSymbolAddress((void**)&sw_p, g_sw);
    cudaGetSymbolAddress((void**)&M_p, g_M);

    // K1: tmp = x_q @ W_in + b_in   (65536x256 @ 256x256)
    sgemm_bias_kernel<<<dim3(C_ / 128, N_ / 128, 1), 256>>>(
        x_q, C_, 0, W_in, C_, 0, tmp_p, C_, 0, b_in, C_);

    // K2: slice weights (softmax over G)
    slicew_kernel<<<(N_ * H_) / 256, 256>>>(W_sl, b_sl, temp);

    // K3: pooling partials
    pool_kernel<<<dim3(NCH2, B_ * H_), 256>>>();

    // K4: tiny attention + fold W_out into M
    attn_tiny_kernel<<<B_ * H_, 256>>>(W_q, b_q, W_k, b_k, W_v, b_v, W_out);

    // K5 (batched over z): out[b] = SW[b](8192x512) @ M[b](512x256) + b_out
    sgemm_bias_kernel<<<dim3(C_ / 128, T_ / 128, B_), 256>>>(
        sw_p, H_ * G_, (size_t)T_ * (H_ * G_),
        M_p, C_, (size_t)(H_ * G_) * C_,
        out, C_, (size_t)T_ * C_,
        b_out, H_ * G_);
}

// round 4
// speedup vs baseline: 1.5695x; 1.3269x over previous
#include <cuda_runtime.h>
#include <cuda_bf16.h>
#include <cstdint>
#include <math.h>

// Problem constants
#define B_ 8
#define T_ 8192
#define C_ 256
#define H_ 8
#define G_ 64
#define D_ 32
#define N_ (B_*T_)
#define CHUNK 128
#define SUBC 4
#define NCH2 16
#define ASTR 40   // smem tile row stride in bf16 elems (80B, conflict-free for ldmatrix)

// ---------------- scratch ------------------------------------------------------
__device__ float g_tmp[(size_t)N_ * C_];
__device__ float g_sw[(size_t)N_ * H_ * G_];
__device__ float g_part[(size_t)B_ * H_ * NCH2 * G_ * D_];
__device__ float g_pnorm[(size_t)B_ * H_ * NCH2 * G_];
__device__ float g_os[(size_t)B_ * H_ * G_ * D_];
// pre-split B operands (transposed: [n][k], bf16 hi/lo)
__device__ __nv_bfloat16 g_Whi[(size_t)C_ * C_];
__device__ __nv_bfloat16 g_Wlo[(size_t)C_ * C_];
__device__ __nv_bfloat16 g_Mhi[(size_t)B_ * C_ * (H_ * G_)];
__device__ __nv_bfloat16 g_Mlo[(size_t)B_ * C_ * (H_ * G_)];

// ---------------- small helpers ------------------------------------------------
__device__ __forceinline__ float2 ffma2(float2 a, float2 b, float2 c) {
    float2 d;
    asm("fma.rn.f32x2 %0, %1, %2, %3;"
        : "=l"(reinterpret_cast<unsigned long long&>(d))
        : "l"(reinterpret_cast<unsigned long long&>(a)),
          "l"(reinterpret_cast<unsigned long long&>(b)),
          "l"(reinterpret_cast<unsigned long long&>(c)));
    return d;
}
__device__ __forceinline__ uint32_t smem_to_u32(const void* p) {
    uint32_t a;
    asm("{ .reg .u64 t; cvta.to.shared.u64 t, %1; cvt.u32.u64 %0, t; }" : "=r"(a) : "l"(p));
    return a;
}
__device__ __forceinline__ void ldsm_x4(uint32_t& r0, uint32_t& r1, uint32_t& r2, uint32_t& r3,
                                        uint32_t addr) {
    asm volatile("ldmatrix.sync.aligned.m8n8.x4.shared.b16 {%0,%1,%2,%3}, [%4];"
                 : "=r"(r0), "=r"(r1), "=r"(r2), "=r"(r3) : "r"(addr));
}
__device__ __forceinline__ void mma_bf16(float* d, const uint32_t* a, uint32_t b0, uint32_t b1) {
    asm volatile("mma.sync.aligned.m16n8k16.row.col.f32.bf16.bf16.f32 "
        "{%0,%1,%2,%3}, {%4,%5,%6,%7}, {%8,%9}, {%0,%1,%2,%3};"
        : "+f"(d[0]), "+f"(d[1]), "+f"(d[2]), "+f"(d[3])
        : "r"(a[0]), "r"(a[1]), "r"(a[2]), "r"(a[3]), "r"(b0), "r"(b1));
}
__device__ __forceinline__ uint32_t bits2(__nv_bfloat162 h) {
    return *reinterpret_cast<uint32_t*>(&h);
}

// ---------------- HMMA split-bf16 GEMM -----------------------------------------
// C[z][M,N] = A[z][M,K](fp32) @ B[z](pre-split bf16, [n][k] layout) + bias
// CTA tile 128x128, k-tile 32, 8 warps (4m x 2n), warp tile 32x64.
__global__ __launch_bounds__(256, 1) void hmma_gemm_kernel(
    const float* __restrict__ A, int lda, size_t strideA,
    const __nv_bfloat16* __restrict__ Bhi, const __nv_bfloat16* __restrict__ Blo,
    size_t strideB,
    float* __restrict__ Cm, int ldc, size_t strideC,
    const float* __restrict__ bias, int K)
{
    __shared__ __align__(16) __nv_bfloat16 sAhi[128 * ASTR];
    __shared__ __align__(16) __nv_bfloat16 sAlo[128 * ASTR];
    __shared__ __align__(16) __nv_bfloat16 sBhi[128 * ASTR];
    __shared__ __align__(16) __nv_bfloat16 sBlo[128 * ASTR];

    const int tid = threadIdx.x;
    const int wid = tid >> 5, lane = tid & 31;
    const int wm = wid & 3, wn = wid >> 2;
    const int m0 = wm * 32, n0w = wn * 64;

    const float* Ab = A + (size_t)blockIdx.z * strideA + (size_t)blockIdx.y * 128 * lda;
    const __nv_bfloat16* Bhb = Bhi + (size_t)blockIdx.z * strideB + (size_t)(blockIdx.x * 128) * K;
    const __nv_bfloat16* Blb = Blo + (size_t)blockIdx.z * strideB + (size_t)(blockIdx.x * 128) * K;
    float* Cb = Cm + (size_t)blockIdx.z * strideC;

    const uint32_t uAhi = smem_to_u32(sAhi), uAlo = smem_to_u32(sAlo);
    const uint32_t uBhi = smem_to_u32(sBhi), uBlo = smem_to_u32(sBlo);

    const int lrow = lane & 15;
    const int lcol = (lane >> 4) * 8;

    float acc[2][8][4];
    #pragma unroll
    for (int mi = 0; mi < 2; mi++)
        #pragma unroll
        for (int n = 0; n < 8; n++)
            #pragma unroll
            for (int q = 0; q < 4; q++) acc[mi][n][q] = 0.f;

    const int arow = tid >> 1;
    const int akh = (tid & 1) << 4;

    for (int kt = 0; kt < K; kt += 32) {
        // ---- A tile: fp32 -> bf16 hi/lo ----
        {
            const float* ap = Ab + (size_t)arow * lda + kt + akh;
            float4 v0 = *(const float4*)(ap);
            float4 v1 = *(const float4*)(ap + 4);
            float4 v2 = *(const float4*)(ap + 8);
            float4 v3 = *(const float4*)(ap + 12);
            float f[16] = {v0.x,v0.y,v0.z,v0.w, v1.x,v1.y,v1.z,v1.w,
                           v2.x,v2.y,v2.z,v2.w, v3.x,v3.y,v3.z,v3.w};
            uint32_t h[8], l[8];
            #pragma unroll
            for (int i = 0; i < 8; i++) {
                __nv_bfloat162 hb = __floats2bfloat162_rn(f[2*i], f[2*i+1]);
                float r0 = f[2*i]   - __bfloat162float(hb.x);
                float r1 = f[2*i+1] - __bfloat162float(hb.y);
                h[i] = bits2(hb);
                l[i] = bits2(__floats2bfloat162_rn(r0, r1));
            }
            uint4* dh = (uint4*)&sAhi[arow * ASTR + akh];
            uint4* dl = (uint4*)&sAlo[arow * ASTR + akh];
            dh[0] = make_uint4(h[0], h[1], h[2], h[3]);
            dh[1] = make_uint4(h[4], h[5], h[6], h[7]);
            dl[0] = make_uint4(l[0], l[1], l[2], l[3]);
            dl[1] = make_uint4(l[4], l[5], l[6], l[7]);
        }
        // ---- B tile: direct bf16 copy (already [n][k]) ----
        {
            const __nv_bfloat16* bph = Bhb + (size_t)arow * K + kt + akh;
            const __nv_bfloat16* bpl = Blb + (size_t)arow * K + kt + akh;
            uint4* dh = (uint4*)&sBhi[arow * ASTR + akh];
            uint4* dl = (uint4*)&sBlo[arow * ASTR + akh];
            dh[0] = *(const uint4*)(bph);
            dh[1] = *(const uint4*)(bph + 8);
            dl[0] = *(const uint4*)(bpl);
            dl[1] = *(const uint4*)(bpl + 8);
        }
        __syncthreads();

        #pragma unroll
        for (int ks = 0; ks < 2; ks++) {
            const int cb = ks * 16 + lcol;
            uint32_t ahi[2][4], alo[2][4], bh[4][4], bl[4][4];
            #pragma unroll
            for (int mi = 0; mi < 2; mi++) {
                uint32_t off = ((m0 + mi * 16 + lrow) * ASTR + cb) * 2;
                ldsm_x4(ahi[mi][0], ahi[mi][1], ahi[mi][2], ahi[mi][3], uAhi + off);
                ldsm_x4(alo[mi][0], alo[mi][1], alo[mi][2], alo[mi][3], uAlo + off);
            }
            #pragma unroll
            for (int nj = 0; nj < 4; nj++) {
                uint32_t off = ((n0w + nj * 16 + lrow) * ASTR + cb) * 2;
                ldsm_x4(bh[nj][0], bh[nj][1], bh[nj][2], bh[nj][3], uBhi + off);
                ldsm_x4(bl[nj][0], bl[nj][1], bl[nj][2], bl[nj][3], uBlo + off);
            }
            #pragma unroll
            for (int mi = 0; mi < 2; mi++) {
                #pragma unroll
                for (int nj = 0; nj < 4; nj++) {
                    float* d0 = acc[mi][nj * 2];
                    mma_bf16(d0, ahi[mi], bh[nj][0], bh[nj][2]);
                    mma_bf16(d0, ahi[mi], bl[nj][0], bl[nj][2]);
                    mma_bf16(d0, alo[mi], bh[nj][0], bh[nj][2]);
                    float* d1 = acc[mi][nj * 2 + 1];
                    mma_bf16(d1, ahi[mi], bh[nj][1], bh[nj][3]);
                    mma_bf16(d1, ahi[mi], bl[nj][1], bl[nj][3]);
                    mma_bf16(d1, alo[mi], bh[nj][1], bh[nj][3]);
                }
            }
        }
        __syncthreads();
    }

    // ---- epilogue ----
    const int grp = lane >> 2, qid = lane & 3;
    #pragma unroll
    for (int mi = 0; mi < 2; mi++) {
        #pragma unroll
        for (int nj = 0; nj < 8; nj++) {
            int row = blockIdx.y * 128 + m0 + mi * 16 + grp;
            int col = blockIdx.x * 128 + n0w + nj * 8 + qid * 2;
            float b0 = bias[col], b1 = bias[col + 1];
            *(float2*)(Cb + (size_t)row * ldc + col) =
                make_float2(acc[mi][nj][0] + b0, acc[mi][nj][1] + b1);
            *(float2*)(Cb + (size_t)(row + 8) * ldc + col) =
                make_float2(acc[mi][nj][2] + b0, acc[mi][nj][3] + b1);
        }
    }
}

// ---------------- prep: split W_in into transposed bf16 hi/lo ------------------
__global__ __launch_bounds__(256) void split_w_kernel(const float* __restrict__ W)
{
    int idx = blockIdx.x * 256 + threadIdx.x;   // k*256 + n
    int k = idx >> 8, n = idx & 255;
    float v = W[idx];
    __nv_bfloat16 h = __float2bfloat16_rn(v);
    g_Whi[(size_t)n * C_ + k] = h;
    g_Wlo[(size_t)n * C_ + k] = __float2bfloat16_rn(v - __bfloat162float(h));
}

// ---------------- K2: slice weights (softmax over G per (n,h)) -----------------
__global__ __launch_bounds__(256) void slicew_kernel(
    const float* __restrict__ Wslice, const float* __restrict__ bslice,
    const float* __restrict__ temp)
{
    __shared__ float Ws[D_ * G_];
    __shared__ float bs[G_];
    __shared__ float it[H_];
    int tid = threadIdx.x;
    #pragma unroll
    for (int i = 0; i < 8; i++) Ws[tid + i * 256] = Wslice[tid + i * 256];
    if (tid < G_) bs[tid] = bslice[tid];
    if (tid < H_) it[tid] = 1.f / temp[tid];
    __syncthreads();

    int gid = blockIdx.x * 256 + tid;
    int n = gid >> 3, h = gid & 7;

    float x[D_];
    const float4* xr = (const float4*)(g_tmp + (size_t)n * C_ + h * D_);
    #pragma unroll
    for (int i = 0; i < 8; i++) {
        float4 v = xr[i];
        x[4*i] = v.x; x[4*i+1] = v.y; x[4*i+2] = v.z; x[4*i+3] = v.w;
    }

    float2 lg[G_ / 2];
    const float2* bs2 = (const float2*)bs;
    #pragma unroll
    for (int j = 0; j < G_ / 2; j++) lg[j] = bs2[j];

    const float2* Ws2 = (const float2*)Ws;
    for (int d = 0; d < D_; d++) {
        float2 xv = make_float2(x[d], x[d]);
        #pragma unroll
        for (int j = 0; j < G_ / 2; j++) lg[j] = ffma2(xv, Ws2[d * (G_ / 2) + j], lg[j]);
    }

    float sc = it[h];
    float mx = -1e30f;
    #pragma unroll
    for (int j = 0; j < G_ / 2; j++) {
        lg[j].x *= sc; lg[j].y *= sc;
        mx = fmaxf(mx, fmaxf(lg[j].x, lg[j].y));
    }
    float sum = 0.f;
    #pragma unroll
    for (int j = 0; j < G_ / 2; j++) {
        lg[j].x = __expf(lg[j].x - mx);
        lg[j].y = __expf(lg[j].y - mx);
        sum += lg[j].x + lg[j].y;
    }
    float inv = 1.f / sum;

    float4* dst = (float4*)(g_sw + (size_t)n * (H_ * G_) + h * G_);
    #pragma unroll
    for (int j = 0; j < 16; j++)
        dst[j] = make_float4(lg[2*j].x * inv, lg[2*j].y * inv,
                             lg[2*j+1].x * inv, lg[2*j+1].y * inv);
}

// ---------------- K3: chunked pooling partials ---------------------------------
__global__ __launch_bounds__(256) void pool_kernel()
{
    __shared__ float xs[CHUNK][D_];
    __shared__ float sws[CHUNK][G_];
    int pc = blockIdx.x, bh = blockIdx.y;
    int b = bh >> 3, h = bh & 7;
    int tid = threadIdx.x;

    int d = tid & 31, gb = (tid >> 5) * 8;
    float2 acc[4] = {{0.f,0.f},{0.f,0.f},{0.f,0.f},{0.f,0.f}};
    float nsum = 0.f;

    for (int sc = 0; sc < SUBC; sc++) {
        size_t nbase = (size_t)b * T_ + ((size_t)pc * SUBC + sc) * CHUNK;
        #pragma unroll
        for (int p = 0; p < 4; p++) {
            int r = (tid >> 3) + p * 32;
            ((float4*)xs[r])[tid & 7] =
                ((const float4*)(g_tmp + (nbase + r) * C_ + h * D_))[tid & 7];
        }
        #pragma unroll
        for (int p = 0; p < 8; p++) {
            int r = (tid >> 4) + p * 16;
            ((float4*)sws[r])[tid & 15] =
                ((const float4*)(g_sw + (nbase + r) * (H_ * G_) + h * G_))[tid & 15];
        }
        __syncthreads();

        for (int r = 0; r < CHUNK; r++) {
            float2 xv = make_float2(xs[r][d], xs[r][d]);
            const float2* swr = (const float2*)&sws[r][gb];
            #pragma unroll
            for (int j = 0; j < 4; j++) acc[j] = ffma2(xv, swr[j], acc[j]);
        }
        if (tid < G_) {
            float s = 0.f;
            for (int r = 0; r < CHUNK; r++) s += sws[r][tid];
            nsum += s;
        }
        __syncthreads();
    }

    size_t pbase = ((size_t)bh * NCH2 + pc) * (G_ * D_);
    #pragma unroll
    for (int j = 0; j < 4; j++) {
        g_part[pbase + (size_t)(gb + 2*j) * D_ + d]     = acc[j].x;
        g_part[pbase + (size_t)(gb + 2*j + 1) * D_ + d] = acc[j].y;
    }
    if (tid < G_)
        g_pnorm[((size_t)bh * NCH2 + pc) * G_ + tid] = nsum;
}

// ------- K4a: reduce partials -> tokens -> qkv -> GxG attention -> g_os --------
__global__ __launch_bounds__(256) void attn_tiny_kernel(
    const float* __restrict__ Wq, const float* __restrict__ bq,
    const float* __restrict__ Wk, const float* __restrict__ bk,
    const float* __restrict__ Wv, const float* __restrict__ bv)
{
    __shared__ float tok[G_][D_ + 1];
    __shared__ float qs[G_][D_ + 1];
    __shared__ float ks[G_][D_ + 1];
    __shared__ float vs[G_][D_ + 1];
    __shared__ float norms[G_];

    int bh = blockIdx.x;
    int tid = threadIdx.x;

    if (tid < G_) {
        float s = 0.f;
        for (int ch = 0; ch < NCH2; ch++)
            s += g_pnorm[((size_t)bh * NCH2 + ch) * G_ + tid];
        norms[tid] = s + 1e-5f;
    }
    __syncthreads();

    #pragma unroll
    for (int i = 0; i < 8; i++) {
        int c = tid + i * 256;
        int g = c >> 5, d = c & 31;
        float s = 0.f;
        for (int ch = 0; ch < NCH2; ch++)
            s += g_part[((size_t)bh * NCH2 + ch) * (G_ * D_) + c];
        tok[g][d] = s / norms[g];
    }
    __syncthreads();

    #pragma unroll
    for (int i = 0; i < 8; i++) {
        int c = tid + i * 256;
        int g = c >> 5, d = c & 31;
        float aq = bq[d], ak = bk[d], av = bv[d];
        for (int e = 0; e < D_; e++) {
            float t = tok[g][e];
            aq += t * Wq[e * D_ + d];
            ak += t * Wk[e * D_ + d];
            av += t * Wv[e * D_ + d];
        }
        qs[g][d] = aq; ks[g][d] = ak; vs[g][d] = av;
    }
    __syncthreads();

    if (tid < G_) {
        float qr[D_];
        #pragma unroll
        for (int d = 0; d < D_; d++) qr[d] = qs[tid][d];
        float s[G_];
        float mx = -1e30f;
        #pragma unroll
        for (int j = 0; j < G_; j++) {
            float a = 0.f;
            #pragma unroll
            for (int d = 0; d < D_; d++) a += qr[d] * ks[j][d];
            a *= 0.17677669529663687f;
            s[j] = a; mx = fmaxf(mx, a);
        }
        float sum = 0.f;
        #pragma unroll
        for (int j = 0; j < G_; j++) { s[j] = __expf(s[j] - mx); sum += s[j]; }
        float inv = 1.f / sum;
        #pragma unroll
        for (int d = 0; d < D_; d++) {
            float a = 0.f;
            #pragma unroll
            for (int j = 0; j < G_; j++) a += s[j] * vs[j][d];
            g_os[(size_t)bh * (G_ * D_) + tid * D_ + d] = a * inv;
        }
    }
}

// ------- K4b: fold into transposed bf16 hi/lo M --------------------------------
// M[b][krow = h*G+g][col] = sum_d os[bh][g][d] * Wout[h*D+d][col], stored [col][krow]
__global__ __launch_bounds__(256) void fold_kernel(const float* __restrict__ Wout)
{
    __shared__ float os[G_][D_ + 1];
    __shared__ float Wt[D_][G_ + 1];
    int bh = blockIdx.y;
    int b = bh >> 3, h = bh & 7;
    int col0 = blockIdx.x * 64;
    int tid = threadIdx.x;

    #pragma unroll
    for (int i = 0; i < 8; i++) {
        int idx = tid + i * 256;
        os[idx >> 5][idx & 31] = g_os[(size_t)bh * (G_ * D_) + idx];
    }
    #pragma unroll
    for (int i = 0; i < 8; i++) {
        int idx = tid + i * 256;
        int d = idx >> 6, c = idx & 63;
        Wt[d][c] = Wout[(size_t)(h * D_ + d) * C_ + col0 + c];
    }
    __syncthreads();

    int c = tid & 63, g0 = tid >> 6;
    #pragma unroll
    for (int gi = 0; gi < 16; gi++) {
        int g = g0 * 16 + gi;
        float a = 0.f;
        #pragma unroll
        for (int d = 0; d < D_; d++) a += os[g][d] * Wt[d][c];
        __nv_bfloat16 hb = __float2bfloat16_rn(a);
        size_t o = ((size_t)b * C_ + col0 + c) * (size_t)(H_ * G_) + h * G_ + g;
        g_Mhi[o] = hb;
        g_Mlo[o] = __float2bfloat16_rn(a - __bfloat162float(hb));
    }
}

// ---------------- launch --------------------------------------------------------
extern "C" void kernel_launch(void* const* d_in, const int* in_sizes, int n_in,
                              void* d_out, int out_size)
{
    const float* x_q    = (const float*)d_in[0];
    const float* W_in   = (const float*)d_in[3];
    const float* b_in   = (const float*)d_in[4];
    const float* W_sl   = (const float*)d_in[5];
    const float* b_sl   = (const float*)d_in[6];
    const float* temp   = (const float*)d_in[7];
    const float* W_q    = (const float*)d_in[8];
    const float* b_q    = (const float*)d_in[9];
    const float* W_k    = (const float*)d_in[10];
    const float* b_k    = (const float*)d_in[11];
    const float* W_v    = (const float*)d_in[12];
    const float* b_v    = (const float*)d_in[13];
    const float* W_out  = (const float*)d_in[14];
    const float* b_out  = (const float*)d_in[15];
    float* out = (float*)d_out;

    float *tmp_p, *sw_p;
    __nv_bfloat16 *whi_p, *wlo_p, *mhi_p, *mlo_p;
    cudaGetSymbolAddress((void**)&tmp_p, g_tmp);
    cudaGetSymbolAddress((void**)&sw_p, g_sw);
    cudaGetSymbolAddress((void**)&whi_p, g_Whi);
    cudaGetSymbolAddress((void**)&wlo_p, g_Wlo);
    cudaGetSymbolAddress((void**)&mhi_p, g_Mhi);
    cudaGetSymbolAddress((void**)&mlo_p, g_Mlo);

    // prep: split W_in
    split_w_kernel<<<C_ * C_ / 256, 256>>>(W_in);

    // K1: tmp = x_q @ W_in + b_in   (HMMA split-bf16)
    hmma_gemm_kernel<<<dim3(C_/128, N_/128, 1), 256>>>(
        x_q, C_, 0, whi_p, wlo_p, 0, tmp_p, C_, 0, b_in, C_);

    // K2: slice softmax
    slicew_kernel<<<(N_ * H_) / 256, 256>>>(W_sl, b_sl, temp);

    // K3: pooling partials
    pool_kernel<<<dim3(NCH2, B_ * H_), 256>>>();

    // K4a: reduce + tiny attention
    attn_tiny_kernel<<<B_ * H_, 256>>>(W_q, b_q, W_k, b_k, W_v, b_v);

    // K4b: fold W_out into pre-split M
    fold_kernel<<<dim3(4, B_ * H_), 256>>>(W_out);

    // K5: out[b] = SW[b] @ M[b] + b_out   (HMMA split-bf16, batched)
    hmma_gemm_kernel<<<dim3(C_/128, T_/128, B_), 256>>>(
        sw_p, H_ * G_, (size_t)T_ * (H_ * G_),
        mhi_p, mlo_p, (size_t)C_ * (H_ * G_),
        out, C_, (size_t)T_ * C_,
        b_out, H_ * G_);
}

// round 5
// speedup vs baseline: 1.9196x; 1.2230x over previous
#include <cuda_runtime.h>
#include <cuda_bf16.h>
#include <cstdint>
#include <math.h>

// Problem constants
#define B_ 8
#define T_ 8192
#define C_ 256
#define H_ 8
#define G_ 64
#define D_ 32
#define N_ (B_*T_)
#define CHUNK 128
#define SUBC 4
#define NCH2 16
#define ASTR 40   // smem tile row stride in bf16 elems (80B, conflict-free for ldmatrix)

// ---------------- scratch ------------------------------------------------------
__device__ float g_tmp[(size_t)N_ * C_];
__device__ float g_sw[(size_t)N_ * H_ * G_];
__device__ float g_part[(size_t)B_ * H_ * NCH2 * G_ * D_];
__device__ float g_pnorm[(size_t)B_ * H_ * NCH2 * G_];
__device__ float g_os[(size_t)B_ * H_ * G_ * D_];
__device__ __nv_bfloat16 g_Whi[(size_t)C_ * C_];
__device__ __nv_bfloat16 g_Wlo[(size_t)C_ * C_];
__device__ __nv_bfloat16 g_Mhi[(size_t)B_ * C_ * (H_ * G_)];
__device__ __nv_bfloat16 g_Mlo[(size_t)B_ * C_ * (H_ * G_)];

// ---------------- small helpers ------------------------------------------------
__device__ __forceinline__ float2 ffma2(float2 a, float2 b, float2 c) {
    float2 d;
    asm("fma.rn.f32x2 %0, %1, %2, %3;"
        : "=l"(reinterpret_cast<unsigned long long&>(d))
        : "l"(reinterpret_cast<unsigned long long&>(a)),
          "l"(reinterpret_cast<unsigned long long&>(b)),
          "l"(reinterpret_cast<unsigned long long&>(c)));
    return d;
}
__device__ __forceinline__ uint32_t smem_to_u32(const void* p) {
    uint32_t a;
    asm("{ .reg .u64 t; cvta.to.shared.u64 t, %1; cvt.u32.u64 %0, t; }" : "=r"(a) : "l"(p));
    return a;
}
__device__ __forceinline__ void ldsm_x4(uint32_t& r0, uint32_t& r1, uint32_t& r2, uint32_t& r3,
                                        uint32_t addr) {
    asm volatile("ldmatrix.sync.aligned.m8n8.x4.shared.b16 {%0,%1,%2,%3}, [%4];"
                 : "=r"(r0), "=r"(r1), "=r"(r2), "=r"(r3) : "r"(addr));
}
__device__ __forceinline__ void mma_bf16(float* d, const uint32_t* a, uint32_t b0, uint32_t b1) {
    asm volatile("mma.sync.aligned.m16n8k16.row.col.f32.bf16.bf16.f32 "
        "{%0,%1,%2,%3}, {%4,%5,%6,%7}, {%8,%9}, {%0,%1,%2,%3};"
        : "+f"(d[0]), "+f"(d[1]), "+f"(d[2]), "+f"(d[3])
        : "r"(a[0]), "r"(a[1]), "r"(a[2]), "r"(a[3]), "r"(b0), "r"(b1));
}
__device__ __forceinline__ uint32_t bits2(__nv_bfloat162 h) {
    return *reinterpret_cast<uint32_t*>(&h);
}
#define CP_ASYNC16(dst, src) \
    asm volatile("cp.async.cg.shared.global [%0], [%1], 16;" :: "r"(dst), "l"(src))
#define CP_COMMIT() asm volatile("cp.async.commit_group;" ::: "memory")
#define CP_WAIT0()  asm volatile("cp.async.wait_group 0;" ::: "memory")

// ---------------- HMMA split-bf16 GEMM, double-buffered ------------------------
// C[z][M,N] = A[z][M,K](fp32) @ B[z](pre-split bf16, [n][k]) + bias
// CTA tile 128x128, k-tile 32, 2 stages, 8 warps (4m x 2n), warp tile 32x64.
#define STG_BYTES (128 * ASTR * 2)            // one buffer: 10240 B
#define STAGE_BYTES (4 * STG_BYTES)           // Ahi,Alo,Bhi,Blo: 40960 B
#define GEMM_SMEM (2 * STAGE_BYTES)           // 81920 B

__global__ __launch_bounds__(256, 1) void hmma_gemm_kernel(
    const float* __restrict__ A, int lda, size_t strideA,
    const __nv_bfloat16* __restrict__ Bhi, const __nv_bfloat16* __restrict__ Blo,
    size_t strideB,
    float* __restrict__ Cm, int ldc, size_t strideC,
    const float* __restrict__ bias, int K)
{
    extern __shared__ __align__(16) char smd[];
    const uint32_t sbase = smem_to_u32(smd);

    const int tid = threadIdx.x;
    const int wid = tid >> 5, lane = tid & 31;
    const int wm = wid & 3, wn = wid >> 2;
    const int m0 = wm * 32, n0w = wn * 64;

    const float* Ab = A + (size_t)blockIdx.z * strideA + (size_t)blockIdx.y * 128 * lda;
    const __nv_bfloat16* Bhb = Bhi + (size_t)blockIdx.z * strideB + (size_t)(blockIdx.x * 128) * K;
    const __nv_bfloat16* Blb = Blo + (size_t)blockIdx.z * strideB + (size_t)(blockIdx.x * 128) * K;
    float* Cb = Cm + (size_t)blockIdx.z * strideC;

    const int lrow = lane & 15;
    const int lcol = (lane >> 4) * 8;

    const int arow = tid >> 1;           // A/B staging row (0..127)
    const int akh  = (tid & 1) << 4;     // k-half (0 or 16)

    // B cp.async mapping: 2 chunks of 16B per buffer per thread
    const int c0row = tid >> 1, c0seg = (tid & 1) * 2;   // chunks tid*2, tid*2+1

    float acc[2][8][4];
    #pragma unroll
    for (int mi = 0; mi < 2; mi++)
        #pragma unroll
        for (int n = 0; n < 8; n++)
            #pragma unroll
            for (int q = 0; q < 4; q++) acc[mi][n][q] = 0.f;

    float fst[16];   // A staging registers

    // offsets inside one stage
    #define OAH 0
    #define OAL STG_BYTES
    #define OBH (2 * STG_BYTES)
    #define OBL (3 * STG_BYTES)

    auto load_A_regs = [&](int kt) {
        const float* ap = Ab + (size_t)arow * lda + kt + akh;
        *(float4*)(fst + 0)  = *(const float4*)(ap);
        *(float4*)(fst + 4)  = *(const float4*)(ap + 4);
        *(float4*)(fst + 8)  = *(const float4*)(ap + 8);
        *(float4*)(fst + 12) = *(const float4*)(ap + 12);
    };
    auto cpasync_B = [&](int kt, int stg) {
        uint32_t dst = sbase + stg * STAGE_BYTES + c0row * (ASTR * 2) + c0seg * 16;
        const char* srch = (const char*)(Bhb + (size_t)c0row * K + kt) + c0seg * 16;
        const char* srcl = (const char*)(Blb + (size_t)c0row * K + kt) + c0seg * 16;
        CP_ASYNC16(dst + OBH, srch);
        CP_ASYNC16(dst + OBH + 16, srch + 16);
        CP_ASYNC16(dst + OBL, srcl);
        CP_ASYNC16(dst + OBL + 16, srcl + 16);
    };
    auto store_A = [&](int stg) {
        uint32_t h[8], l[8];
        #pragma unroll
        for (int i = 0; i < 8; i++) {
            __nv_bfloat162 hb = __floats2bfloat162_rn(fst[2*i], fst[2*i+1]);
            float r0 = fst[2*i]   - __bfloat162float(hb.x);
            float r1 = fst[2*i+1] - __bfloat162float(hb.y);
            h[i] = bits2(hb);
            l[i] = bits2(__floats2bfloat162_rn(r0, r1));
        }
        char* dh = smd + stg * STAGE_BYTES + OAH + arow * (ASTR * 2) + akh * 2;
        char* dl = smd + stg * STAGE_BYTES + OAL + arow * (ASTR * 2) + akh * 2;
        ((uint4*)dh)[0] = make_uint4(h[0], h[1], h[2], h[3]);
        ((uint4*)dh)[1] = make_uint4(h[4], h[5], h[6], h[7]);
        ((uint4*)dl)[0] = make_uint4(l[0], l[1], l[2], l[3]);
        ((uint4*)dl)[1] = make_uint4(l[4], l[5], l[6], l[7]);
    };

    // prologue: fill stage 0
    load_A_regs(0);
    cpasync_B(0, 0);
    CP_COMMIT();
    store_A(0);
    CP_WAIT0();
    __syncthreads();

    int stage = 0;
    for (int kt = 0; kt < K; kt += 32) {
        const bool has_next = (kt + 32 < K);
        if (has_next) {
            load_A_regs(kt + 32);
            cpasync_B(kt + 32, stage ^ 1);
            CP_COMMIT();
        }

        const uint32_t sb = sbase + stage * STAGE_BYTES;
        #pragma unroll
        for (int ks = 0; ks < 2; ks++) {
            const int cb = ks * 16 + lcol;
            uint32_t ahi[2][4], alo[2][4], bh[4][4], bl[4][4];
            #pragma unroll
            for (int mi = 0; mi < 2; mi++) {
                uint32_t off = ((m0 + mi * 16 + lrow) * ASTR + cb) * 2;
                ldsm_x4(ahi[mi][0], ahi[mi][1], ahi[mi][2], ahi[mi][3], sb + OAH + off);
                ldsm_x4(alo[mi][0], alo[mi][1], alo[mi][2], alo[mi][3], sb + OAL + off);
            }
            #pragma unroll
            for (int nj = 0; nj < 4; nj++) {
                uint32_t off = ((n0w + nj * 16 + lrow) * ASTR + cb) * 2;
                ldsm_x4(bh[nj][0], bh[nj][1], bh[nj][2], bh[nj][3], sb + OBH + off);
                ldsm_x4(bl[nj][0], bl[nj][1], bl[nj][2], bl[nj][3], sb + OBL + off);
            }
            #pragma unroll
            for (int mi = 0; mi < 2; mi++) {
                #pragma unroll
                for (int nj = 0; nj < 4; nj++) {
                    float* d0 = acc[mi][nj * 2];
                    mma_bf16(d0, ahi[mi], bh[nj][0], bh[nj][2]);
                    mma_bf16(d0, ahi[mi], bl[nj][0], bl[nj][2]);
                    mma_bf16(d0, alo[mi], bh[nj][0], bh[nj][2]);
                    float* d1 = acc[mi][nj * 2 + 1];
                    mma_bf16(d1, ahi[mi], bh[nj][1], bh[nj][3]);
                    mma_bf16(d1, ahi[mi], bl[nj][1], bl[nj][3]);
                    mma_bf16(d1, alo[mi], bh[nj][1], bh[nj][3]);
                }
            }
        }

        if (has_next) {
            store_A(stage ^ 1);
            CP_WAIT0();
            __syncthreads();
            stage ^= 1;
        }
    }

    // ---- epilogue ----
    const int grp = lane >> 2, qid = lane & 3;
    #pragma unroll
    for (int mi = 0; mi < 2; mi++) {
        #pragma unroll
        for (int nj = 0; nj < 8; nj++) {
            int row = blockIdx.y * 128 + m0 + mi * 16 + grp;
            int col = blockIdx.x * 128 + n0w + nj * 8 + qid * 2;
            float b0 = bias[col], b1 = bias[col + 1];
            *(float2*)(Cb + (size_t)row * ldc + col) =
                make_float2(acc[mi][nj][0] + b0, acc[mi][nj][1] + b1);
            *(float2*)(Cb + (size_t)(row + 8) * ldc + col) =
                make_float2(acc[mi][nj][2] + b0, acc[mi][nj][3] + b1);
        }
    }
}

// ---------------- prep: split W_in into transposed bf16 hi/lo ------------------
__global__ __launch_bounds__(256) void split_w_kernel(const float* __restrict__ W)
{
    int idx = blockIdx.x * 256 + threadIdx.x;   // k*256 + n
    int k = idx >> 8, n = idx & 255;
    float v = W[idx];
    __nv_bfloat16 h = __float2bfloat16_rn(v);
    g_Whi[(size_t)n * C_ + k] = h;
    g_Wlo[(size_t)n * C_ + k] = __float2bfloat16_rn(v - __bfloat162float(h));
}

// ---------------- K2: slice weights (softmax over G per (n,h)) -----------------
__global__ __launch_bounds__(256) void slicew_kernel(
    const float* __restrict__ Wslice, const float* __restrict__ bslice,
    const float* __restrict__ temp)
{
    __shared__ float Ws[D_ * G_];
    __shared__ float bs[G_];
    __shared__ float it[H_];
    int tid = threadIdx.x;
    #pragma unroll
    for (int i = 0; i < 8; i++) Ws[tid + i * 256] = Wslice[tid + i * 256];
    if (tid < G_) bs[tid] = bslice[tid];
    if (tid < H_) it[tid] = 1.f / temp[tid];
    __syncthreads();

    int gid = blockIdx.x * 256 + tid;
    int n = gid >> 3, h = gid & 7;

    float x[D_];
    const float4* xr = (const float4*)(g_tmp + (size_t)n * C_ + h * D_);
    #pragma unroll
    for (int i = 0; i < 8; i++) {
        float4 v = xr[i];
        x[4*i] = v.x; x[4*i+1] = v.y; x[4*i+2] = v.z; x[4*i+3] = v.w;
    }

    float2 lg[G_ / 2];
    const float2* bs2 = (const float2*)bs;
    #pragma unroll
    for (int j = 0; j < G_ / 2; j++) lg[j] = bs2[j];

    const float2* Ws2 = (const float2*)Ws;
    for (int d = 0; d < D_; d++) {
        float2 xv = make_float2(x[d], x[d]);
        #pragma unroll
        for (int j = 0; j < G_ / 2; j++) lg[j] = ffma2(xv, Ws2[d * (G_ / 2) + j], lg[j]);
    }

    float sc = it[h];
    float mx = -1e30f;
    #pragma unroll
    for (int j = 0; j < G_ / 2; j++) {
        lg[j].x *= sc; lg[j].y *= sc;
        mx = fmaxf(mx, fmaxf(lg[j].x, lg[j].y));
    }
    float sum = 0.f;
    #pragma unroll
    for (int j = 0; j < G_ / 2; j++) {
        lg[j].x = __expf(lg[j].x - mx);
        lg[j].y = __expf(lg[j].y - mx);
        sum += lg[j].x + lg[j].y;
    }
    float inv = 1.f / sum;

    float4* dst = (float4*)(g_sw + (size_t)n * (H_ * G_) + h * G_);
    #pragma unroll
    for (int j = 0; j < 16; j++)
        dst[j] = make_float4(lg[2*j].x * inv, lg[2*j].y * inv,
                             lg[2*j+1].x * inv, lg[2*j+1].y * inv);
}

// ---------------- K3: chunked pooling partials ---------------------------------
__global__ __launch_bounds__(256) void pool_kernel()
{
    __shared__ float xs[CHUNK][D_];
    __shared__ __align__(16) float sws[CHUNK][G_];
    int pc = blockIdx.x, bh = blockIdx.y;
    int b = bh >> 3, h = bh & 7;
    int tid = threadIdx.x;

    int d = tid & 31, gb = (tid >> 5) * 8;
    float2 acc[4] = {{0.f,0.f},{0.f,0.f},{0.f,0.f},{0.f,0.f}};
    float nsum = 0.f;

    for (int sc = 0; sc < SUBC; sc++) {
        size_t nbase = (size_t)b * T_ + ((size_t)pc * SUBC + sc) * CHUNK;
        #pragma unroll
        for (int p = 0; p < 4; p++) {
            int r = (tid >> 3) + p * 32;
            ((float4*)xs[r])[tid & 7] =
                ((const float4*)(g_tmp + (nbase + r) * C_ + h * D_))[tid & 7];
        }
        #pragma unroll
        for (int p = 0; p < 8; p++) {
            int r = (tid >> 4) + p * 16;
            ((float4*)sws[r])[tid & 15] =
                ((const float4*)(g_sw + (nbase + r) * (H_ * G_) + h * G_))[tid & 15];
        }
        __syncthreads();

        #pragma unroll 4
        for (int r = 0; r < CHUNK; r++) {
            float2 xv = make_float2(xs[r][d], xs[r][d]);
            const float4* swr4 = (const float4*)&sws[r][gb];
            float4 w0 = swr4[0], w1 = swr4[1];
            acc[0] = ffma2(xv, make_float2(w0.x, w0.y), acc[0]);
            acc[1] = ffma2(xv, make_float2(w0.z, w0.w), acc[1]);
            acc[2] = ffma2(xv, make_float2(w1.x, w1.y), acc[2]);
            acc[3] = ffma2(xv, make_float2(w1.z, w1.w), acc[3]);
        }
        if (tid < G_) {
            float s = 0.f;
            for (int r = 0; r < CHUNK; r++) s += sws[r][tid];
            nsum += s;
        }
        __syncthreads();
    }

    size_t pbase = ((size_t)bh * NCH2 + pc) * (G_ * D_);
    #pragma unroll
    for (int j = 0; j < 4; j++) {
        g_part[pbase + (size_t)(gb + 2*j) * D_ + d]     = acc[j].x;
        g_part[pbase + (size_t)(gb + 2*j + 1) * D_ + d] = acc[j].y;
    }
    if (tid < G_)
        g_pnorm[((size_t)bh * NCH2 + pc) * G_ + tid] = nsum;
}

// ------- K4a: reduce partials -> tokens -> qkv -> GxG attention -> g_os --------
__global__ __launch_bounds__(256) void attn_tiny_kernel(
    const float* __restrict__ Wq, const float* __restrict__ bq,
    const float* __restrict__ Wk, const float* __restrict__ bk,
    const float* __restrict__ Wv, const float* __restrict__ bv)
{
    __shared__ float tok[G_][D_ + 1];
    __shared__ float qs[G_][D_ + 1];
    __shared__ float ks[G_][D_ + 1];
    __shared__ float vs[G_][D_ + 1];
    __shared__ float norms[G_];

    int bh = blockIdx.x;
    int tid = threadIdx.x;

    if (tid < G_) {
        float s = 0.f;
        for (int ch = 0; ch < NCH2; ch++)
            s += g_pnorm[((size_t)bh * NCH2 + ch) * G_ + tid];
        norms[tid] = s + 1e-5f;
    }
    __syncthreads();

    #pragma unroll
    for (int i = 0; i < 8; i++) {
        int c = tid + i * 256;
        int g = c >> 5, d = c & 31;
        float s = 0.f;
        for (int ch = 0; ch < NCH2; ch++)
            s += g_part[((size_t)bh * NCH2 + ch) * (G_ * D_) + c];
        tok[g][d] = s / norms[g];
    }
    __syncthreads();

    #pragma unroll
    for (int i = 0; i < 8; i++) {
        int c = tid + i * 256;
        int g = c >> 5, d = c & 31;
        float aq = bq[d], ak = bk[d], av = bv[d];
        for (int e = 0; e < D_; e++) {
            float t = tok[g][e];
            aq += t * Wq[e * D_ + d];
            ak += t * Wk[e * D_ + d];
            av += t * Wv[e * D_ + d];
        }
        qs[g][d] = aq; ks[g][d] = ak; vs[g][d] = av;
    }
    __syncthreads();

    if (tid < G_) {
        float qr[D_];
        #pragma unroll
        for (int d = 0; d < D_; d++) qr[d] = qs[tid][d];
        float s[G_];
        float mx = -1e30f;
        #pragma unroll
        for (int j = 0; j < G_; j++) {
            float a = 0.f;
            #pragma unroll
            for (int d = 0; d < D_; d++) a += qr[d] * ks[j][d];
            a *= 0.17677669529663687f;
            s[j] = a; mx = fmaxf(mx, a);
        }
        float sum = 0.f;
        #pragma unroll
        for (int j = 0; j < G_; j++) { s[j] = __expf(s[j] - mx); sum += s[j]; }
        float inv = 1.f / sum;
        #pragma unroll
        for (int d = 0; d < D_; d++) {
            float a = 0.f;
            #pragma unroll
            for (int j = 0; j < G_; j++) a += s[j] * vs[j][d];
            g_os[(size_t)bh * (G_ * D_) + tid * D_ + d] = a * inv;
        }
    }
}

// ------- K4b: fold into transposed bf16 hi/lo M --------------------------------
__global__ __launch_bounds__(256) void fold_kernel(const float* __restrict__ Wout)
{
    __shared__ float os[G_][D_ + 1];
    __shared__ float Wt[D_][G_ + 1];
    int bh = blockIdx.y;
    int b = bh >> 3, h = bh & 7;
    int col0 = blockIdx.x * 64;
    int tid = threadIdx.x;

    #pragma unroll
    for (int i = 0; i < 8; i++) {
        int idx = tid + i * 256;
        os[idx >> 5][idx & 31] = g_os[(size_t)bh * (G_ * D_) + idx];
    }
    #pragma unroll
    for (int i = 0; i < 8; i++) {
        int idx = tid + i * 256;
        int d = idx >> 6, c = idx & 63;
        Wt[d][c] = Wout[(size_t)(h * D_ + d) * C_ + col0 + c];
    }
    __syncthreads();

    int c = tid & 63, g0 = tid >> 6;
    #pragma unroll
    for (int gi = 0; gi < 16; gi++) {
        int g = g0 * 16 + gi;
        float a = 0.f;
        #pragma unroll
        for (int d = 0; d < D_; d++) a += os[g][d] * Wt[d][c];
        __nv_bfloat16 hb = __float2bfloat16_rn(a);
        size_t o = ((size_t)b * C_ + col0 + c) * (size_t)(H_ * G_) + h * G_ + g;
        g_Mhi[o] = hb;
        g_Mlo[o] = __float2bfloat16_rn(a - __bfloat162float(hb));
    }
}

// ---------------- launch --------------------------------------------------------
extern "C" void kernel_launch(void* const* d_in, const int* in_sizes, int n_in,
                              void* d_out, int out_size)
{
    const float* x_q    = (const float*)d_in[0];
    const float* W_in   = (const float*)d_in[3];
    const float* b_in   = (const float*)d_in[4];
    const float* W_sl   = (const float*)d_in[5];
    const float* b_sl   = (const float*)d_in[6];
    const float* temp   = (const float*)d_in[7];
    const float* W_q    = (const float*)d_in[8];
    const float* b_q    = (const float*)d_in[9];
    const float* W_k    = (const float*)d_in[10];
    const float* b_k    = (const float*)d_in[11];
    const float* W_v    = (const float*)d_in[12];
    const float* b_v    = (const float*)d_in[13];
    const float* W_out  = (const float*)d_in[14];
    const float* b_out  = (const float*)d_in[15];
    float* out = (float*)d_out;

    float *tmp_p, *sw_p;
    __nv_bfloat16 *whi_p, *wlo_p, *mhi_p, *mlo_p;
    cudaGetSymbolAddress((void**)&tmp_p, g_tmp);
    cudaGetSymbolAddress((void**)&sw_p, g_sw);
    cudaGetSymbolAddress((void**)&whi_p, g_Whi);
    cudaGetSymbolAddress((void**)&wlo_p, g_Wlo);
    cudaGetSymbolAddress((void**)&mhi_p, g_Mhi);
    cudaGetSymbolAddress((void**)&mlo_p, g_Mlo);

    static int smem_set = 0;
    if (!smem_set) {
        cudaFuncSetAttribute(hmma_gemm_kernel,
                             cudaFuncAttributeMaxDynamicSharedMemorySize, GEMM_SMEM);
        smem_set = 1;
    }

    // prep: split W_in
    split_w_kernel<<<C_ * C_ / 256, 256>>>(W_in);

    // K1: tmp = x_q @ W_in + b_in
    hmma_gemm_kernel<<<dim3(C_/128, N_/128, 1), 256, GEMM_SMEM>>>(
        x_q, C_, 0, whi_p, wlo_p, 0, tmp_p, C_, 0, b_in, C_);

    // K2: slice softmax
    slicew_kernel<<<(N_ * H_) / 256, 256>>>(W_sl, b_sl, temp);

    // K3: pooling partials
    pool_kernel<<<dim3(NCH2, B_ * H_), 256>>>();

    // K4a: reduce + tiny attention
    attn_tiny_kernel<<<B_ * H_, 256>>>(W_q, b_q, W_k, b_k, W_v, b_v);

    // K4b: fold W_out into pre-split M
    fold_kernel<<<dim3(4, B_ * H_), 256>>>(W_out);

    // K5: out[b] = SW[b] @ M[b] + b_out
    hmma_gemm_kernel<<<dim3(C_/128, T_/128, B_), 256, GEMM_SMEM>>>(
        sw_p, H_ * G_, (size_t)T_ * (H_ * G_),
        mhi_p, mlo_p, (size_t)C_ * (H_ * G_),
        out, C_, (size_t)T_ * C_,
        b_out, H_ * G_);
}